// round 6
// baseline (speedup 1.0000x reference)
#include <cuda_runtime.h>
#include <cuda_fp16.h>
#include <cstdint>

// ---------------- problem constants ----------------------------------------
#define TREES   512
#define TSIZE   400
#define NNODES  (TREES * TSIZE)   // 204800
#define INFEAT  768
#define HFEAT   256
#define G3      768

// level geometry (ternary tree, 400 nodes):
//  d:      0    1    2    3     4     5      6
//  cnt:    1    3    9    27    81    243    36
//  start:  0    1    4    13    40    121    364     (start[d]=3*start[d-1]+1)
//  level-major row offsets: 0 512 2048 6656 20480 61952 186368
//  parents for level d = first PC[d] locals of level d-1; PC: 1 3 9 27 81 12
//  every parent has exactly 3 children: child_local = 3*lp + k
//  leaves: level-5 locals 12..242 + all level-6

// ---------------- scratch (device bss) ---------------------------------------
__device__ __half g_gx16[(size_t)NNODES * G3];         // input gates fp16
__device__ float  g_h32 [(size_t)NNODES * HFEAT];      // hiddens fp32, level-major
__device__ __half g_h16 [(size_t)NNODES * HFEAT];      // hiddens fp16, level-major
__device__ __half g_x16 [(size_t)NNODES * INFEAT];     // fp16 inputs
__device__ __half g_wih [3 * HFEAT * INFEAT];          // fp16 W_ih
__device__ __half g_whh [3 * HFEAT * HFEAT];           // fp16 W_hh

// ---------------- PTX helpers ------------------------------------------------
__device__ __forceinline__ void mma_f16(float* c, const uint32_t* a, const uint32_t* b) {
    asm volatile(
        "mma.sync.aligned.m16n8k16.row.col.f32.f16.f16.f32 "
        "{%0,%1,%2,%3}, {%4,%5,%6,%7}, {%8,%9}, {%0,%1,%2,%3};"
        : "+f"(c[0]), "+f"(c[1]), "+f"(c[2]), "+f"(c[3])
        : "r"(a[0]), "r"(a[1]), "r"(a[2]), "r"(a[3]), "r"(b[0]), "r"(b[1]));
}
__device__ __forceinline__ void ldsm4(uint32_t* r, uint32_t saddr) {
    asm volatile("ldmatrix.sync.aligned.m8n8.x4.shared.b16 {%0,%1,%2,%3}, [%4];"
        : "=r"(r[0]), "=r"(r[1]), "=r"(r[2]), "=r"(r[3]) : "r"(saddr));
}
__device__ __forceinline__ void cp16(uint32_t saddr, const void* g) {
    asm volatile("cp.async.cg.shared.global [%0], [%1], 16;" :: "r"(saddr), "l"(g));
}
__device__ __forceinline__ void cp_commit() { asm volatile("cp.async.commit_group;"); }
template <int N> __device__ __forceinline__ void cp_wait() {
    asm volatile("cp.async.wait_group %0;" :: "n"(N));
}

// fast accurate sigmoid/tanh: ex2.approx + rcp.approx (~1e-6 rel err)
__device__ __forceinline__ float sigx(float x) {
    float e, r;
    asm("ex2.approx.f32 %0, %1;" : "=f"(e) : "f"(-x * 1.4426950408889634f));
    asm("rcp.approx.f32 %0, %1;" : "=f"(r) : "f"(1.0f + e));
    return r;
}
__device__ __forceinline__ float tanhx(float x) {
    float e, r;
    asm("ex2.approx.f32 %0, %1;" : "=f"(e) : "f"(-x * 2.8853900817779268f));
    asm("rcp.approx.f32 %0, %1;" : "=f"(r) : "f"(1.0f + e));
    return __fmaf_rn(2.0f, r, -1.0f);
}

// ======================= gx GEMM (R5 mainloop, fp16 out) =====================
#define BM 128
#define BN 256
#define BK 64
#define NS 4
#define BKP 72
#define A_STAGE_B (BM * BKP * 2)
#define B_STAGE_B (BN * BKP * 2)
#define STAGE_B   (A_STAGE_B + B_STAGE_B)
#define SMEM_GX   (NS * STAGE_B)                 // 221184
#define NTHR 512

__global__ void __launch_bounds__(NTHR, 1)
gemm_gx(const __half* __restrict__ A, const __half* __restrict__ B,
        const float* __restrict__ bias, __half* __restrict__ C)
{
    extern __shared__ char smem[];
    const uint32_t sbase = (uint32_t)__cvta_generic_to_shared(smem);
    const int tid  = threadIdx.x;
    const int lane = tid & 31, warp = tid >> 5;
    const int wm = (warp >> 3) * 64;
    const int wn = (warp & 7) * 32;
    const int col0 = blockIdx.x * BN;
    const int row0 = blockIdx.y * BM;
    const int KT = INFEAT / BK;                  // 12

    const __half* asrc[2]; uint32_t adst[2];
    #pragma unroll
    for (int i = 0; i < 2; ++i) {
        int lin = tid + i * NTHR, r = lin >> 3, cc = lin & 7;
        asrc[i] = A + (size_t)(row0 + r) * INFEAT + cc * 8;
        adst[i] = (uint32_t)((r * BKP + cc * 8) * 2);
    }
    const __half* bsrc[4]; uint32_t bdst[4];
    #pragma unroll
    for (int i = 0; i < 4; ++i) {
        int lin = tid + i * NTHR, r = lin >> 3, cc = lin & 7;
        bsrc[i] = B + (size_t)(col0 + r) * INFEAT + cc * 8;
        bdst[i] = (uint32_t)((r * BKP + cc * 8) * 2);
    }
    auto issue = [&](int kt) {
        uint32_t sa = sbase + (uint32_t)(kt & (NS - 1)) * STAGE_B;
        uint32_t sb = sa + A_STAGE_B;
        const int ko = kt * BK;
        #pragma unroll
        for (int i = 0; i < 2; ++i) cp16(sa + adst[i], asrc[i] + ko);
        #pragma unroll
        for (int i = 0; i < 4; ++i) cp16(sb + bdst[i], bsrc[i] + ko);
    };

    const int j = lane >> 3, sub = lane & 7;
    uint32_t aoff[4], boff[2];
    #pragma unroll
    for (int mi = 0; mi < 4; ++mi) {
        int arow = wm + mi * 16 + (j & 1) * 8 + sub;
        aoff[mi] = (uint32_t)(arow * BKP * 2 + (j >> 1) * 16);
    }
    #pragma unroll
    for (int p = 0; p < 2; ++p) {
        int brow = wn + p * 16 + ((lane >> 4) & 1) * 8 + sub;
        boff[p] = (uint32_t)(brow * BKP * 2 + ((lane >> 3) & 1) * 16);
    }

    float acc[4][4][4];
    #pragma unroll
    for (int mi = 0; mi < 4; ++mi)
        #pragma unroll
        for (int ni = 0; ni < 4; ++ni)
            #pragma unroll
            for (int v = 0; v < 4; ++v) acc[mi][ni][v] = 0.f;

    #pragma unroll
    for (int s = 0; s < NS - 1; ++s) { issue(s); cp_commit(); }

    for (int kt = 0; kt < KT; ++kt) {
        cp_wait<NS - 2>();
        __syncthreads();
        int nk = kt + NS - 1;
        if (nk < KT) issue(nk);
        cp_commit();

        uint32_t sA = sbase + (uint32_t)(kt & (NS - 1)) * STAGE_B;
        uint32_t sB = sA + A_STAGE_B;
        #pragma unroll
        for (int kk = 0; kk < BK / 16; ++kk) {
            const uint32_t kb = kk * 32;
            uint32_t afr[4][4], bfr[2][4];
            #pragma unroll
            for (int mi = 0; mi < 4; ++mi) ldsm4(afr[mi], sA + aoff[mi] + kb);
            #pragma unroll
            for (int p = 0; p < 2; ++p)   ldsm4(bfr[p], sB + boff[p] + kb);
            #pragma unroll
            for (int mi = 0; mi < 4; ++mi) {
                #pragma unroll
                for (int p = 0; p < 2; ++p) {
                    mma_f16(acc[mi][2 * p],     afr[mi], &bfr[p][0]);
                    mma_f16(acc[mi][2 * p + 1], afr[mi], &bfr[p][2]);
                }
            }
        }
    }

    // epilogue: bias fp32, store fp16
    const int g = lane >> 2, tig = lane & 3;
    #pragma unroll
    for (int mi = 0; mi < 4; ++mi) {
        int row = row0 + wm + mi * 16 + g;
        #pragma unroll
        for (int ni = 0; ni < 4; ++ni) {
            int col = col0 + wn + ni * 8 + 2 * tig;
            float b0 = bias[col], b1 = bias[col + 1];
            *(__half2*)(C + (size_t)row * G3 + col) =
                __floats2half2_rn(acc[mi][ni][0] + b0, acc[mi][ni][1] + b1);
            *(__half2*)(C + (size_t)(row + 8) * G3 + col) =
                __floats2half2_rn(acc[mi][ni][2] + b0, acc[mi][ni][3] + b1);
        }
    }
}

// ======================= fused gh-GEMM + GRU level kernel ====================
// grid (2, M/128): bx = h-col half (128 cols), by = parent row block.
// A (parent h16, full K=256) resident in smem; B = 3 gate slices of W_hh,
// streamed in 4 K-chunks of 64, double-buffered. Epilogue applies GRU to the
// 3 children of each parent directly from accumulators.
#define AKP 264                                   // A row stride (halves)
#define FA_BYTES (128 * AKP * 2)                  // 67584
#define FB_STG   (3 * 128 * BKP * 2)              // 55296
#define SMEM_FU  (FA_BYTES + 2 * FB_STG)          // 178176

__global__ void __launch_bounds__(256, 1)
gru_level(const __half* __restrict__ Whh, const float* __restrict__ b_hh,
          int PC, int CNTP, int CNTD, int STARTD, int OFFP, int OFFD, int NPC)
{
    extern __shared__ char smem[];
    const uint32_t sA = (uint32_t)__cvta_generic_to_shared(smem);
    const uint32_t sB = sA + FA_BYTES;
    const int tid  = threadIdx.x;
    const int lane = tid & 31, warp = tid >> 5;
    const int wm = (warp >> 2) * 64;              // 2 M-groups
    const int wn = (warp & 3) * 32;               // 4 n-groups (128 cols)
    const int c0 = blockIdx.x * 128;
    const int row0 = blockIdx.y * 128;

    // ---- stage A: 128 rows x 256 halves (gathered parent rows) ----
    #pragma unroll
    for (int i = 0; i < 16; ++i) {
        int lin = tid + i * 256;
        int r = lin >> 5, cc = lin & 31;
        int grow = row0 + r;
        int t = grow / PC, lp = grow - t * PC;
        const __half* src = g_h16 + ((size_t)(OFFP + t * CNTP + lp) * HFEAT + cc * 8);
        cp16(sA + (uint32_t)((r * AKP + cc * 8) * 2), src);
    }
    cp_commit();

    // ---- B staging: per stage, 3 gates x 128 rows x 64 halves ----
    auto issueB = [&](int kt) {
        uint32_t base = sB + (uint32_t)(kt & 1) * FB_STG;
        #pragma unroll
        for (int i = 0; i < 12; ++i) {
            int lin = tid + i * 256;
            int gg = lin >> 10, rowc = (lin >> 3) & 127, cc = lin & 7;
            const __half* src = Whh + ((size_t)(gg * HFEAT + c0 + rowc) * HFEAT
                                       + kt * 64 + cc * 8);
            cp16(base + (uint32_t)(((gg * 128 + rowc) * BKP + cc * 8) * 2), src);
        }
        cp_commit();
    };
    issueB(0);

    // ldmatrix offsets
    const int j = lane >> 3, sub = lane & 7;
    uint32_t aoff[4];
    #pragma unroll
    for (int mi = 0; mi < 4; ++mi) {
        int arow = wm + mi * 16 + (j & 1) * 8 + sub;
        aoff[mi] = (uint32_t)(arow * AKP * 2 + (j >> 1) * 16);
    }
    uint32_t boffp[2];
    #pragma unroll
    for (int p = 0; p < 2; ++p) {
        int brow = wn + p * 16 + ((lane >> 4) & 1) * 8 + sub;
        boffp[p] = (uint32_t)(brow * BKP * 2 + ((lane >> 3) & 1) * 16);
    }

    float acc[3][4][4][4];
    #pragma unroll
    for (int gg = 0; gg < 3; ++gg)
        #pragma unroll
        for (int mi = 0; mi < 4; ++mi)
            #pragma unroll
            for (int ni = 0; ni < 4; ++ni)
                #pragma unroll
                for (int v = 0; v < 4; ++v) acc[gg][mi][ni][v] = 0.f;

    for (int kt = 0; kt < 4; ++kt) {
        __syncthreads();                          // buffer reuse guard
        if (kt + 1 < 4) { issueB(kt + 1); cp_wait<1>(); }
        else            { cp_wait<0>(); }
        __syncthreads();

        uint32_t bbase = sB + (uint32_t)(kt & 1) * FB_STG;
        #pragma unroll
        for (int kk = 0; kk < 4; ++kk) {
            uint32_t akb = (uint32_t)(kt * 128 + kk * 32);
            uint32_t bkb = (uint32_t)(kk * 32);
            uint32_t afr[4][4];
            #pragma unroll
            for (int mi = 0; mi < 4; ++mi) ldsm4(afr[mi], sA + aoff[mi] + akb);
            #pragma unroll
            for (int gg = 0; gg < 3; ++gg) {
                uint32_t bfr[2][4];
                uint32_t gb = bbase + (uint32_t)(gg * 128 * BKP * 2);
                ldsm4(bfr[0], gb + boffp[0] + bkb);
                ldsm4(bfr[1], gb + boffp[1] + bkb);
                #pragma unroll
                for (int mi = 0; mi < 4; ++mi) {
                    mma_f16(acc[gg][mi][0], afr[mi], &bfr[0][0]);
                    mma_f16(acc[gg][mi][1], afr[mi], &bfr[0][2]);
                    mma_f16(acc[gg][mi][2], afr[mi], &bfr[1][0]);
                    mma_f16(acc[gg][mi][3], afr[mi], &bfr[1][2]);
                }
            }
        }
    }

    // ---- fused GRU epilogue ----
    const int quad = lane >> 2, tig = lane & 3;
    float2 bb[3][4];
    #pragma unroll
    for (int gg = 0; gg < 3; ++gg)
        #pragma unroll
        for (int ni = 0; ni < 4; ++ni)
            bb[gg][ni] = *(const float2*)(b_hh + gg * HFEAT + c0 + wn + ni * 8 + 2 * tig);

    #pragma unroll
    for (int mi = 0; mi < 4; ++mi) {
        #pragma unroll
        for (int hh = 0; hh < 2; ++hh) {
            int grow = row0 + wm + mi * 16 + quad + hh * 8;
            int t = grow / PC, lp = grow - t * PC;
            size_t prow  = (size_t)(OFFP + t * CNTP + lp);
            size_t crow0 = (size_t)(OFFD + t * CNTD + 3 * lp);
            size_t node0 = (size_t)(t * TSIZE + STARTD + 3 * lp);
            int storeh16_0 = (3 * lp + 0 < NPC);
            int storeh16_1 = (3 * lp + 1 < NPC);
            int storeh16_2 = (3 * lp + 2 < NPC);
            #pragma unroll
            for (int ni = 0; ni < 4; ++ni) {
                int jc = c0 + wn + ni * 8 + 2 * tig;
                float2 hp = *(const float2*)(g_h32 + prow * HFEAT + jc);
                float ghr0 = acc[0][mi][ni][2 * hh]     + bb[0][ni].x;
                float ghr1 = acc[0][mi][ni][2 * hh + 1] + bb[0][ni].y;
                float ghz0 = acc[1][mi][ni][2 * hh]     + bb[1][ni].x;
                float ghz1 = acc[1][mi][ni][2 * hh + 1] + bb[1][ni].y;
                float ghn0 = acc[2][mi][ni][2 * hh]     + bb[2][ni].x;
                float ghn1 = acc[2][mi][ni][2 * hh + 1] + bb[2][ni].y;
                #pragma unroll
                for (int k = 0; k < 3; ++k) {
                    const __half* gxb = g_gx16 + (node0 + k) * G3 + jc;
                    float2 xr = __half22float2(*(const __half2*)(gxb));
                    float2 xz = __half22float2(*(const __half2*)(gxb + HFEAT));
                    float2 xn = __half22float2(*(const __half2*)(gxb + 2 * HFEAT));
                    float r0 = sigx(xr.x + ghr0), r1 = sigx(xr.y + ghr1);
                    float z0 = sigx(xz.x + ghz0), z1 = sigx(xz.y + ghz1);
                    float n0 = tanhx(xn.x + r0 * ghn0), n1 = tanhx(xn.y + r1 * ghn1);
                    float h0 = (1.0f - z0) * n0 + z0 * hp.x;
                    float h1 = (1.0f - z1) * n1 + z1 * hp.y;
                    float* hw = g_h32 + (crow0 + k) * HFEAT + jc;
                    *(float2*)hw = make_float2(h0, h1);
                    int sh = (k == 0) ? storeh16_0 : (k == 1) ? storeh16_1 : storeh16_2;
                    if (sh)
                        *(__half2*)(g_h16 + (crow0 + k) * HFEAT + jc) =
                            __floats2half2_rn(h0, h1);
                }
            }
        }
    }
}

// ---------------- misc kernels ------------------------------------------------
__global__ void f2h(const float* __restrict__ in, __half* __restrict__ out, int n8) {
    int i = blockIdx.x * 256 + threadIdx.x;
    if (i >= n8) return;
    const float4* p = (const float4*)in + i * 2;
    float4 v0 = p[0], v1 = p[1];
    __half2 h0 = __floats2half2_rn(v0.x, v0.y);
    __half2 h1 = __floats2half2_rn(v0.z, v0.w);
    __half2 h2 = __floats2half2_rn(v1.x, v1.y);
    __half2 h3 = __floats2half2_rn(v1.z, v1.w);
    uint4 u;
    u.x = *(uint32_t*)&h0; u.y = *(uint32_t*)&h1;
    u.z = *(uint32_t*)&h2; u.w = *(uint32_t*)&h3;
    *((uint4*)out + i) = u;
}

__global__ void ew_level0(const float* __restrict__ b_hh) {
    int t = blockIdx.x, j = threadIdx.x;
    const __half* gx = g_gx16 + (size_t)(t * TSIZE) * G3;
    float xr = __half2float(gx[j]);
    float xz = __half2float(gx[HFEAT + j]);
    float xn = __half2float(gx[2 * HFEAT + j]);
    float r = sigx(xr + b_hh[j]);
    float z = sigx(xz + b_hh[HFEAT + j]);
    float n = tanhx(xn + r * b_hh[2 * HFEAT + j]);
    float h = (1.0f - z) * n;
    g_h32[(size_t)t * HFEAT + j] = h;
    g_h16[(size_t)t * HFEAT + j] = __float2half_rn(h);
}

__global__ void leaf_max(float* __restrict__ out) {
    int t = blockIdx.x, j = threadIdx.x;
    float m = -3.402823466e+38f;
    const float* h5 = g_h32 + (size_t)(61952 + t * 243) * HFEAT;
    #pragma unroll 4
    for (int ls = 12; ls < 243; ++ls) m = fmaxf(m, h5[(size_t)ls * HFEAT + j]);
    const float* h6 = g_h32 + (size_t)(186368 + t * 36) * HFEAT;
    #pragma unroll 4
    for (int ls = 0; ls < 36; ++ls)   m = fmaxf(m, h6[(size_t)ls * HFEAT + j]);
    out[(size_t)t * HFEAT + j] = m;
}

// ---------------- launch -------------------------------------------------------
extern "C" void kernel_launch(void* const* d_in, const int* in_sizes, int n_in,
                              void* d_out, int out_size) {
    const float* inputs = (const float*)d_in[0];
    const float* W_ih   = (const float*)d_in[1];
    const float* W_hh   = (const float*)d_in[2];
    const float* b_ih   = (const float*)d_in[3];
    const float* b_hh   = (const float*)d_in[4];
    float* out = (float*)d_out;

    __half *p_gx16, *p_x16, *p_wih, *p_whh;
    cudaGetSymbolAddress((void**)&p_gx16, g_gx16);
    cudaGetSymbolAddress((void**)&p_x16,  g_x16);
    cudaGetSymbolAddress((void**)&p_wih,  g_wih);
    cudaGetSymbolAddress((void**)&p_whh,  g_whh);

    cudaFuncSetAttribute(gemm_gx,
                         cudaFuncAttributeMaxDynamicSharedMemorySize, SMEM_GX);
    cudaFuncSetAttribute(gru_level,
                         cudaFuncAttributeMaxDynamicSharedMemorySize, SMEM_FU);

    static const int cnt[7]   = {1, 3, 9, 27, 81, 243, 36};
    static const int start[7] = {0, 1, 4, 13, 40, 121, 364};
    static const int off[7]   = {0, 512, 2048, 6656, 20480, 61952, 186368};
    static const int PC[8]    = {0, 1, 3, 9, 27, 81, 12, 0};

    // 0) fp16 conversions
    f2h<<<(NNODES * INFEAT / 8 + 255) / 256, 256>>>(inputs, p_x16, NNODES * INFEAT / 8);
    f2h<<<(3 * HFEAT * INFEAT / 8 + 255) / 256, 256>>>(W_ih, p_wih, 3 * HFEAT * INFEAT / 8);
    f2h<<<(3 * HFEAT * HFEAT / 8 + 255) / 256, 256>>>(W_hh, p_whh, 3 * HFEAT * HFEAT / 8);

    // 1) gx = inputs @ W_ih^T + b_ih  (fp16 out)
    gemm_gx<<<dim3(G3 / BN, NNODES / BM), NTHR, SMEM_GX>>>(p_x16, p_wih, b_ih, p_gx16);

    // 2) roots
    ew_level0<<<TREES, 256>>>(b_hh);

    // 3) levels 1..6: fused parent-GEMM + GRU
    for (int d = 1; d < 7; ++d) {
        int M = PC[d] * TREES;
        gru_level<<<dim3(2, M / 128), 256, SMEM_FU>>>(
            p_whh, b_hh, PC[d], cnt[d - 1], cnt[d], start[d],
            off[d - 1], off[d], PC[d + 1]);
    }

    // 4) leaf max
    leaf_max<<<TREES, 256>>>(out);

    (void)in_sizes; (void)n_in; (void)out_size;
}

// round 7
// speedup vs baseline: 1.3500x; 1.3500x over previous
#include <cuda_runtime.h>
#include <cuda_fp16.h>
#include <cstdint>

// ---------------- problem constants ----------------------------------------
#define TREES   512
#define TSIZE   400
#define NNODES  (TREES * TSIZE)   // 204800
#define INFEAT  768
#define HFEAT   256
#define G3      768

// level geometry (ternary tree, 400 nodes):
//  d:      0    1    2    3     4     5      6
//  cnt:    1    3    9    27    81    243    36
//  start:  0    1    4    13    40    121    364
//  level-major row offsets: 0 512 2048 6656 20480 61952 186368
//  parents for level d = first PC[d] locals of level d-1; PC: 1 3 9 27 81 12
//  leaves: level-5 locals 12..242 + all level-6

// ---------------- scratch (device bss) ---------------------------------------
__device__ __half g_gx16[(size_t)NNODES * G3];         // input gates fp16
__device__ float  g_h32 [(size_t)NNODES * HFEAT];      // hiddens fp32, level-major
__device__ __half g_h16 [(size_t)NNODES * HFEAT];      // hiddens fp16 (parents only)
__device__ __half g_gh16[(size_t)(81 * TREES) * G3];   // parent gates fp16
__device__ __half g_x16 [(size_t)NNODES * INFEAT];     // fp16 inputs
__device__ __half g_wih [3 * HFEAT * INFEAT];          // fp16 W_ih
__device__ __half g_whh [3 * HFEAT * HFEAT];           // fp16 W_hh

// ---------------- PTX helpers ------------------------------------------------
__device__ __forceinline__ void mma_f16(float* c, const uint32_t* a, const uint32_t* b) {
    asm volatile(
        "mma.sync.aligned.m16n8k16.row.col.f32.f16.f16.f32 "
        "{%0,%1,%2,%3}, {%4,%5,%6,%7}, {%8,%9}, {%0,%1,%2,%3};"
        : "+f"(c[0]), "+f"(c[1]), "+f"(c[2]), "+f"(c[3])
        : "r"(a[0]), "r"(a[1]), "r"(a[2]), "r"(a[3]), "r"(b[0]), "r"(b[1]));
}
__device__ __forceinline__ void ldsm4(uint32_t* r, uint32_t saddr) {
    asm volatile("ldmatrix.sync.aligned.m8n8.x4.shared.b16 {%0,%1,%2,%3}, [%4];"
        : "=r"(r[0]), "=r"(r[1]), "=r"(r[2]), "=r"(r[3]) : "r"(saddr));
}
__device__ __forceinline__ void cp16(uint32_t saddr, const void* g) {
    asm volatile("cp.async.cg.shared.global [%0], [%1], 16;" :: "r"(saddr), "l"(g));
}
__device__ __forceinline__ void cp_commit() { asm volatile("cp.async.commit_group;"); }
template <int N> __device__ __forceinline__ void cp_wait() {
    asm volatile("cp.async.wait_group %0;" :: "n"(N));
}

// fast accurate sigmoid/tanh: ex2.approx + rcp.approx (~1e-6 rel err)
__device__ __forceinline__ float sigx(float x) {
    float e, r;
    asm("ex2.approx.f32 %0, %1;" : "=f"(e) : "f"(-x * 1.4426950408889634f));
    asm("rcp.approx.f32 %0, %1;" : "=f"(r) : "f"(1.0f + e));
    return r;
}
__device__ __forceinline__ float tanhx(float x) {
    float e, r;
    asm("ex2.approx.f32 %0, %1;" : "=f"(e) : "f"(-x * 2.8853900817779268f));
    asm("rcp.approx.f32 %0, %1;" : "=f"(r) : "f"(1.0f + e));
    return __fmaf_rn(2.0f, r, -1.0f);
}

// ================= fp16 GEMM: C16[M,768] = A16[M,KDIM]*B16^T + bias ==========
// GATHER: logical row r -> A row (r/PC)*STR + r%PC  (parent-subset remap)
#define BM 128
#define BN 256
#define BK 64
#define NS 4
#define BKP 72
#define A_STAGE_B (BM * BKP * 2)
#define B_STAGE_B (BN * BKP * 2)
#define STAGE_B   (A_STAGE_B + B_STAGE_B)
#define SMEM_GX   (NS * STAGE_B)                 // 221184
#define NTHR 512

template <int KDIM, bool GATHER>
__global__ void __launch_bounds__(NTHR, 1)
gemm_h(const __half* __restrict__ A, const __half* __restrict__ B,
       const float* __restrict__ bias, __half* __restrict__ C,
       int PC, int STR)
{
    extern __shared__ char smem[];
    const uint32_t sbase = (uint32_t)__cvta_generic_to_shared(smem);
    const int tid  = threadIdx.x;
    const int lane = tid & 31, warp = tid >> 5;
    const int wm = (warp >> 3) * 64;
    const int wn = (warp & 7) * 32;
    const int col0 = blockIdx.x * BN;
    const int row0 = blockIdx.y * BM;
    const int KT = KDIM / BK;

    const __half* asrc[2]; uint32_t adst[2];
    #pragma unroll
    for (int i = 0; i < 2; ++i) {
        int lin = tid + i * NTHR, r = lin >> 3, cc = lin & 7;
        int rr = row0 + r, gr;
        if (GATHER) { int t = rr / PC; gr = t * STR + (rr - t * PC); }
        else        { gr = rr; }
        asrc[i] = A + (size_t)gr * KDIM + cc * 8;
        adst[i] = (uint32_t)((r * BKP + cc * 8) * 2);
    }
    const __half* bsrc[4]; uint32_t bdst[4];
    #pragma unroll
    for (int i = 0; i < 4; ++i) {
        int lin = tid + i * NTHR, r = lin >> 3, cc = lin & 7;
        bsrc[i] = B + (size_t)(col0 + r) * KDIM + cc * 8;
        bdst[i] = (uint32_t)((r * BKP + cc * 8) * 2);
    }
    auto issue = [&](int kt) {
        uint32_t sa = sbase + (uint32_t)(kt & (NS - 1)) * STAGE_B;
        uint32_t sb = sa + A_STAGE_B;
        const int ko = kt * BK;
        #pragma unroll
        for (int i = 0; i < 2; ++i) cp16(sa + adst[i], asrc[i] + ko);
        #pragma unroll
        for (int i = 0; i < 4; ++i) cp16(sb + bdst[i], bsrc[i] + ko);
    };

    const int j = lane >> 3, sub = lane & 7;
    uint32_t aoff[4], boff[2];
    #pragma unroll
    for (int mi = 0; mi < 4; ++mi) {
        int arow = wm + mi * 16 + (j & 1) * 8 + sub;
        aoff[mi] = (uint32_t)(arow * BKP * 2 + (j >> 1) * 16);
    }
    #pragma unroll
    for (int p = 0; p < 2; ++p) {
        int brow = wn + p * 16 + ((lane >> 4) & 1) * 8 + sub;
        boff[p] = (uint32_t)(brow * BKP * 2 + ((lane >> 3) & 1) * 16);
    }

    float acc[4][4][4];
    #pragma unroll
    for (int mi = 0; mi < 4; ++mi)
        #pragma unroll
        for (int ni = 0; ni < 4; ++ni)
            #pragma unroll
            for (int v = 0; v < 4; ++v) acc[mi][ni][v] = 0.f;

    #pragma unroll
    for (int s = 0; s < NS - 1; ++s) { issue(s); cp_commit(); }

    for (int kt = 0; kt < KT; ++kt) {
        cp_wait<NS - 2>();
        __syncthreads();
        int nk = kt + NS - 1;
        if (nk < KT) issue(nk);
        cp_commit();

        uint32_t sA = sbase + (uint32_t)(kt & (NS - 1)) * STAGE_B;
        uint32_t sB = sA + A_STAGE_B;
        #pragma unroll
        for (int kk = 0; kk < BK / 16; ++kk) {
            const uint32_t kb = kk * 32;
            uint32_t afr[4][4], bfr[2][4];
            #pragma unroll
            for (int mi = 0; mi < 4; ++mi) ldsm4(afr[mi], sA + aoff[mi] + kb);
            #pragma unroll
            for (int p = 0; p < 2; ++p)   ldsm4(bfr[p], sB + boff[p] + kb);
            #pragma unroll
            for (int mi = 0; mi < 4; ++mi) {
                #pragma unroll
                for (int p = 0; p < 2; ++p) {
                    mma_f16(acc[mi][2 * p],     afr[mi], &bfr[p][0]);
                    mma_f16(acc[mi][2 * p + 1], afr[mi], &bfr[p][2]);
                }
            }
        }
    }

    // epilogue: bias fp32, store fp16
    const int g = lane >> 2, tig = lane & 3;
    #pragma unroll
    for (int mi = 0; mi < 4; ++mi) {
        int row = row0 + wm + mi * 16 + g;
        #pragma unroll
        for (int ni = 0; ni < 4; ++ni) {
            int col = col0 + wn + ni * 8 + 2 * tig;
            float b0 = bias[col], b1 = bias[col + 1];
            *(__half2*)(C + (size_t)row * G3 + col) =
                __floats2half2_rn(acc[mi][ni][0] + b0, acc[mi][ni][1] + b1);
            *(__half2*)(C + (size_t)(row + 8) * G3 + col) =
                __floats2half2_rn(acc[mi][ni][2] + b0, acc[mi][ni][3] + b1);
        }
    }
}

// ---------------- misc kernels ------------------------------------------------
__global__ void f2h(const float* __restrict__ in, __half* __restrict__ out, int n8) {
    int i = blockIdx.x * 256 + threadIdx.x;
    if (i >= n8) return;
    const float4* p = (const float4*)in + i * 2;
    float4 v0 = p[0], v1 = p[1];
    __half2 h0 = __floats2half2_rn(v0.x, v0.y);
    __half2 h1 = __floats2half2_rn(v0.z, v0.w);
    __half2 h2 = __floats2half2_rn(v1.x, v1.y);
    __half2 h3 = __floats2half2_rn(v1.z, v1.w);
    uint4 u;
    u.x = *(uint32_t*)&h0; u.y = *(uint32_t*)&h1;
    u.z = *(uint32_t*)&h2; u.w = *(uint32_t*)&h3;
    *((uint4*)out + i) = u;
}

__global__ void ew_level0(const float* __restrict__ b_hh) {
    int t = blockIdx.x, j = threadIdx.x;
    const __half* gx = g_gx16 + (size_t)(t * TSIZE) * G3;
    float xr = __half2float(gx[j]);
    float xz = __half2float(gx[HFEAT + j]);
    float xn = __half2float(gx[2 * HFEAT + j]);
    float r = sigx(xr + b_hh[j]);
    float z = sigx(xz + b_hh[HFEAT + j]);
    float n = tanhx(xn + r * b_hh[2 * HFEAT + j]);
    float h = (1.0f - z) * n;
    g_h32[(size_t)t * HFEAT + j] = h;
    g_h16[(size_t)t * HFEAT + j] = __float2half_rn(h);
}

// level d>=1: gh16 from parent-subset GEMM (PC rows per tree), bias included
__global__ void ew_level(int cnt_d, int cnt_p, int start_d, int start_p,
                         int off_d, int off_p, int PC, int NPC) {
    int idx = blockIdx.x * blockDim.x + threadIdx.x;     // cnt_d*TREES*HFEAT
    int p = idx >> 8, j = idx & 255;
    int t = p / cnt_d;
    int ls = p - t * cnt_d;                               // local child idx
    int s  = start_d + ls;
    int lp = (s - 1) / 3 - start_p;                       // parent local idx
    int ghrow = t * PC + lp;
    int hrow  = off_p + t * cnt_p + lp;
    float hp = g_h32[(size_t)hrow * HFEAT + j];
    const __half* gx = g_gx16 + (size_t)(t * TSIZE + s) * G3;
    const __half* gh = g_gh16 + (size_t)ghrow * G3;
    float r = sigx(__half2float(gx[j]) + __half2float(gh[j]));
    float z = sigx(__half2float(gx[HFEAT + j]) + __half2float(gh[HFEAT + j]));
    float n = tanhx(__half2float(gx[2 * HFEAT + j])
                    + r * __half2float(gh[2 * HFEAT + j]));
    float h = (1.0f - z) * n + z * hp;
    g_h32[(size_t)(off_d + p) * HFEAT + j] = h;
    if (ls < NPC)                                         // parent of next level
        g_h16[(size_t)(off_d + p) * HFEAT + j] = __float2half_rn(h);
}

__global__ void leaf_max(float* __restrict__ out) {
    int t = blockIdx.x, j = threadIdx.x;
    float m = -3.402823466e+38f;
    const float* h5 = g_h32 + (size_t)(61952 + t * 243) * HFEAT;
    #pragma unroll 4
    for (int ls = 12; ls < 243; ++ls) m = fmaxf(m, h5[(size_t)ls * HFEAT + j]);
    const float* h6 = g_h32 + (size_t)(186368 + t * 36) * HFEAT;
    #pragma unroll 4
    for (int ls = 0; ls < 36; ++ls)   m = fmaxf(m, h6[(size_t)ls * HFEAT + j]);
    out[(size_t)t * HFEAT + j] = m;
}

// ---------------- launch -------------------------------------------------------
extern "C" void kernel_launch(void* const* d_in, const int* in_sizes, int n_in,
                              void* d_out, int out_size) {
    const float* inputs = (const float*)d_in[0];
    const float* W_ih   = (const float*)d_in[1];
    const float* W_hh   = (const float*)d_in[2];
    const float* b_ih   = (const float*)d_in[3];
    const float* b_hh   = (const float*)d_in[4];
    float* out = (float*)d_out;

    __half *p_gx16, *p_gh16, *p_x16, *p_wih, *p_whh, *p_h16;
    cudaGetSymbolAddress((void**)&p_gx16, g_gx16);
    cudaGetSymbolAddress((void**)&p_gh16, g_gh16);
    cudaGetSymbolAddress((void**)&p_x16,  g_x16);
    cudaGetSymbolAddress((void**)&p_wih,  g_wih);
    cudaGetSymbolAddress((void**)&p_whh,  g_whh);
    cudaGetSymbolAddress((void**)&p_h16,  g_h16);

    cudaFuncSetAttribute(gemm_h<INFEAT, false>,
                         cudaFuncAttributeMaxDynamicSharedMemorySize, SMEM_GX);
    cudaFuncSetAttribute(gemm_h<HFEAT, true>,
                         cudaFuncAttributeMaxDynamicSharedMemorySize, SMEM_GX);

    static const int cnt[7]   = {1, 3, 9, 27, 81, 243, 36};
    static const int start[7] = {0, 1, 4, 13, 40, 121, 364};
    static const int off[7]   = {0, 512, 2048, 6656, 20480, 61952, 186368};
    static const int PC[8]    = {0, 1, 3, 9, 27, 81, 12, 0};

    // 0) fp16 conversions
    f2h<<<(NNODES * INFEAT / 8 + 255) / 256, 256>>>(inputs, p_x16, NNODES * INFEAT / 8);
    f2h<<<(3 * HFEAT * INFEAT / 8 + 255) / 256, 256>>>(W_ih, p_wih, 3 * HFEAT * INFEAT / 8);
    f2h<<<(3 * HFEAT * HFEAT / 8 + 255) / 256, 256>>>(W_hh, p_whh, 3 * HFEAT * HFEAT / 8);

    // 1) gx = inputs @ W_ih^T + b_ih  (fp16 out)
    gemm_h<INFEAT, false><<<dim3(G3 / BN, NNODES / BM), NTHR, SMEM_GX>>>(
        p_x16, p_wih, b_ih, p_gx16, 1, 1);

    // 2) roots
    ew_level0<<<TREES, 256>>>(b_hh);

    // 3) levels 1..6: parent-subset gh GEMM (fp16 out, bias fused) + GRU ew
    for (int d = 1; d < 7; ++d) {
        int M = PC[d] * TREES;
        gemm_h<HFEAT, true><<<dim3(G3 / BN, M / BM), NTHR, SMEM_GX>>>(
            p_h16 + (size_t)off[d - 1] * HFEAT, p_whh, b_hh, p_gh16,
            PC[d], cnt[d - 1]);
        int R = cnt[d] * TREES;
        ew_level<<<R, 256>>>(cnt[d], cnt[d - 1], start[d], start[d - 1],
                             off[d], off[d - 1], PC[d], PC[d + 1]);
    }

    // 4) leaf max
    leaf_max<<<TREES, 256>>>(out);

    (void)in_sizes; (void)n_in; (void)out_size;
}

// round 8
// speedup vs baseline: 1.3666x; 1.0123x over previous
#include <cuda_runtime.h>
#include <cuda_fp16.h>
#include <cstdint>

// ---------------- problem constants ----------------------------------------
#define TREES   512
#define TSIZE   400
#define NNODES  (TREES * TSIZE)   // 204800
#define INFEAT  768
#define HFEAT   256
#define G3      768

// level geometry (ternary tree, 400 nodes):
//  d:      0    1    2    3     4     5      6
//  cnt:    1    3    9    27    81    243    36
//  start:  0    1    4    13    40    121    364
//  level-major row offsets: 0 512 2048 6656 20480 61952 186368
//  parents for level d = first PC[d] locals of level d-1; PC: 1 3 9 27 81 12
//  leaves: level-5 locals 12..242 + all level-6

// ---------------- scratch (device bss) ---------------------------------------
__device__ __half g_gx16[(size_t)NNODES * G3];         // input gates fp16
__device__ float  g_h32 [(size_t)NNODES * HFEAT];      // hiddens fp32, level-major
__device__ __half g_h16 [(size_t)NNODES * HFEAT];      // hiddens fp16 (parents only)
__device__ __half g_gh16[(size_t)(81 * TREES) * G3];   // parent gates fp16
__device__ __half g_x16 [(size_t)NNODES * INFEAT];     // fp16 inputs
__device__ __half g_wih [3 * HFEAT * INFEAT];          // fp16 W_ih
__device__ __half g_whh [3 * HFEAT * HFEAT];           // fp16 W_hh

// ---------------- PTX helpers ------------------------------------------------
__device__ __forceinline__ void mma_f16(float* c, const uint32_t* a, const uint32_t* b) {
    asm volatile(
        "mma.sync.aligned.m16n8k16.row.col.f32.f16.f16.f32 "
        "{%0,%1,%2,%3}, {%4,%5,%6,%7}, {%8,%9}, {%0,%1,%2,%3};"
        : "+f"(c[0]), "+f"(c[1]), "+f"(c[2]), "+f"(c[3])
        : "r"(a[0]), "r"(a[1]), "r"(a[2]), "r"(a[3]), "r"(b[0]), "r"(b[1]));
}
__device__ __forceinline__ void ldsm4(uint32_t* r, uint32_t saddr) {
    asm volatile("ldmatrix.sync.aligned.m8n8.x4.shared.b16 {%0,%1,%2,%3}, [%4];"
        : "=r"(r[0]), "=r"(r[1]), "=r"(r[2]), "=r"(r[3]) : "r"(saddr));
}
__device__ __forceinline__ void cp16(uint32_t saddr, const void* g) {
    asm volatile("cp.async.cg.shared.global [%0], [%1], 16;" :: "r"(saddr), "l"(g));
}
__device__ __forceinline__ void cp_commit() { asm volatile("cp.async.commit_group;"); }
template <int N> __device__ __forceinline__ void cp_wait() {
    asm volatile("cp.async.wait_group %0;" :: "n"(N));
}

// fast accurate sigmoid/tanh: ex2.approx + rcp.approx (~1e-6 rel err)
__device__ __forceinline__ float sigx(float x) {
    float e, r;
    asm("ex2.approx.f32 %0, %1;" : "=f"(e) : "f"(-x * 1.4426950408889634f));
    asm("rcp.approx.f32 %0, %1;" : "=f"(r) : "f"(1.0f + e));
    return r;
}
__device__ __forceinline__ float tanhx(float x) {
    float e, r;
    asm("ex2.approx.f32 %0, %1;" : "=f"(e) : "f"(-x * 2.8853900817779268f));
    asm("rcp.approx.f32 %0, %1;" : "=f"(r) : "f"(1.0f + e));
    return __fmaf_rn(2.0f, r, -1.0f);
}

// ================= fp16 GEMM: C16[M,768] = A16[M,KDIM]*B16^T + bias ==========
// Tiles: BM=128, BN=128, BK=64, NS=3, 256 threads -> 110592 B smem, 2 CTAs/SM.
// GATHER: logical row r -> A row (r/PC)*STR + r%PC  (parent-subset remap)
#define BM 128
#define BN 128
#define BK 64
#define NS 3
#define BKP 72
#define A_STAGE_B (BM * BKP * 2)                 // 18432
#define B_STAGE_B (BN * BKP * 2)                 // 18432
#define STAGE_B   (A_STAGE_B + B_STAGE_B)        // 36864
#define SMEM_GX   (NS * STAGE_B)                 // 110592
#define NTHR 256

template <int KDIM, bool GATHER>
__global__ void __launch_bounds__(NTHR, 2)
gemm_h(const __half* __restrict__ A, const __half* __restrict__ B,
       const float* __restrict__ bias, __half* __restrict__ C,
       int PC, int STR)
{
    extern __shared__ char smem[];
    const uint32_t sbase = (uint32_t)__cvta_generic_to_shared(smem);
    const int tid  = threadIdx.x;
    const int lane = tid & 31, warp = tid >> 5;
    const int wm = (warp >> 2) * 64;             // 2 warp-groups along M
    const int wn = (warp & 3) * 32;              // 4 along N
    const int col0 = blockIdx.x * BN;
    const int row0 = blockIdx.y * BM;
    const int KT = KDIM / BK;

    const __half* asrc[4]; uint32_t adst[4];
    #pragma unroll
    for (int i = 0; i < 4; ++i) {
        int lin = tid + i * NTHR, r = lin >> 3, cc = lin & 7;
        int rr = row0 + r, gr;
        if (GATHER) { int t = rr / PC; gr = t * STR + (rr - t * PC); }
        else        { gr = rr; }
        asrc[i] = A + (size_t)gr * KDIM + cc * 8;
        adst[i] = (uint32_t)((r * BKP + cc * 8) * 2);
    }
    const __half* bsrc[4]; uint32_t bdst[4];
    #pragma unroll
    for (int i = 0; i < 4; ++i) {
        int lin = tid + i * NTHR, r = lin >> 3, cc = lin & 7;
        bsrc[i] = B + (size_t)(col0 + r) * KDIM + cc * 8;
        bdst[i] = (uint32_t)((r * BKP + cc * 8) * 2);
    }
    auto issue = [&](int kt) {
        uint32_t sa = sbase + (uint32_t)(kt % NS) * STAGE_B;
        uint32_t sb = sa + A_STAGE_B;
        const int ko = kt * BK;
        #pragma unroll
        for (int i = 0; i < 4; ++i) cp16(sa + adst[i], asrc[i] + ko);
        #pragma unroll
        for (int i = 0; i < 4; ++i) cp16(sb + bdst[i], bsrc[i] + ko);
    };

    const int j = lane >> 3, sub = lane & 7;
    uint32_t aoff[4], boff[2];
    #pragma unroll
    for (int mi = 0; mi < 4; ++mi) {
        int arow = wm + mi * 16 + (j & 1) * 8 + sub;
        aoff[mi] = (uint32_t)(arow * BKP * 2 + (j >> 1) * 16);
    }
    #pragma unroll
    for (int p = 0; p < 2; ++p) {
        int brow = wn + p * 16 + ((lane >> 4) & 1) * 8 + sub;
        boff[p] = (uint32_t)(brow * BKP * 2 + ((lane >> 3) & 1) * 16);
    }

    float acc[4][4][4];
    #pragma unroll
    for (int mi = 0; mi < 4; ++mi)
        #pragma unroll
        for (int ni = 0; ni < 4; ++ni)
            #pragma unroll
            for (int v = 0; v < 4; ++v) acc[mi][ni][v] = 0.f;

    #pragma unroll
    for (int s = 0; s < NS - 1; ++s) { issue(s); cp_commit(); }

    for (int kt = 0; kt < KT; ++kt) {
        cp_wait<NS - 2>();
        __syncthreads();
        int nk = kt + NS - 1;
        if (nk < KT) issue(nk);
        cp_commit();

        uint32_t sA = sbase + (uint32_t)(kt % NS) * STAGE_B;
        uint32_t sB = sA + A_STAGE_B;
        #pragma unroll
        for (int kk = 0; kk < BK / 16; ++kk) {
            const uint32_t kb = kk * 32;
            uint32_t afr[4][4], bfr[2][4];
            #pragma unroll
            for (int mi = 0; mi < 4; ++mi) ldsm4(afr[mi], sA + aoff[mi] + kb);
            #pragma unroll
            for (int p = 0; p < 2; ++p)   ldsm4(bfr[p], sB + boff[p] + kb);
            #pragma unroll
            for (int mi = 0; mi < 4; ++mi) {
                #pragma unroll
                for (int p = 0; p < 2; ++p) {
                    mma_f16(acc[mi][2 * p],     afr[mi], &bfr[p][0]);
                    mma_f16(acc[mi][2 * p + 1], afr[mi], &bfr[p][2]);
                }
            }
        }
        __syncthreads();
    }

    // epilogue: bias fp32, store fp16
    const int g = lane >> 2, tig = lane & 3;
    #pragma unroll
    for (int mi = 0; mi < 4; ++mi) {
        int row = row0 + wm + mi * 16 + g;
        #pragma unroll
        for (int ni = 0; ni < 4; ++ni) {
            int col = col0 + wn + ni * 8 + 2 * tig;
            float b0 = bias[col], b1 = bias[col + 1];
            *(__half2*)(C + (size_t)row * G3 + col) =
                __floats2half2_rn(acc[mi][ni][0] + b0, acc[mi][ni][1] + b1);
            *(__half2*)(C + (size_t)(row + 8) * G3 + col) =
                __floats2half2_rn(acc[mi][ni][2] + b0, acc[mi][ni][3] + b1);
        }
    }
}

// ---------------- misc kernels ------------------------------------------------
__global__ void f2h(const float* __restrict__ in, __half* __restrict__ out, int n8) {
    int i = blockIdx.x * 256 + threadIdx.x;
    if (i >= n8) return;
    const float4* p = (const float4*)in + i * 2;
    float4 v0 = p[0], v1 = p[1];
    __half2 h0 = __floats2half2_rn(v0.x, v0.y);
    __half2 h1 = __floats2half2_rn(v0.z, v0.w);
    __half2 h2 = __floats2half2_rn(v1.x, v1.y);
    __half2 h3 = __floats2half2_rn(v1.z, v1.w);
    uint4 u;
    u.x = *(uint32_t*)&h0; u.y = *(uint32_t*)&h1;
    u.z = *(uint32_t*)&h2; u.w = *(uint32_t*)&h3;
    *((uint4*)out + i) = u;
}

__global__ void ew_level0(const float* __restrict__ b_hh) {
    int t = blockIdx.x, j = threadIdx.x;
    const __half* gx = g_gx16 + (size_t)(t * TSIZE) * G3;
    float xr = __half2float(gx[j]);
    float xz = __half2float(gx[HFEAT + j]);
    float xn = __half2float(gx[2 * HFEAT + j]);
    float r = sigx(xr + b_hh[j]);
    float z = sigx(xz + b_hh[HFEAT + j]);
    float n = tanhx(xn + r * b_hh[2 * HFEAT + j]);
    float h = (1.0f - z) * n;
    g_h32[(size_t)t * HFEAT + j] = h;
    g_h16[(size_t)t * HFEAT + j] = __float2half_rn(h);
}

// level d>=1: gh16 from parent-subset GEMM (PC rows per tree), bias included
__global__ void ew_level(int cnt_d, int cnt_p, int start_d, int start_p,
                         int off_d, int off_p, int PC, int NPC) {
    int idx = blockIdx.x * blockDim.x + threadIdx.x;     // cnt_d*TREES*HFEAT
    int p = idx >> 8, j = idx & 255;
    int t = p / cnt_d;
    int ls = p - t * cnt_d;                               // local child idx
    int s  = start_d + ls;
    int lp = (s - 1) / 3 - start_p;                       // parent local idx
    int ghrow = t * PC + lp;
    int hrow  = off_p + t * cnt_p + lp;
    float hp = g_h32[(size_t)hrow * HFEAT + j];
    const __half* gx = g_gx16 + (size_t)(t * TSIZE + s) * G3;
    const __half* gh = g_gh16 + (size_t)ghrow * G3;
    float r = sigx(__half2float(gx[j]) + __half2float(gh[j]));
    float z = sigx(__half2float(gx[HFEAT + j]) + __half2float(gh[HFEAT + j]));
    float n = tanhx(__half2float(gx[2 * HFEAT + j])
                    + r * __half2float(gh[2 * HFEAT + j]));
    float h = (1.0f - z) * n + z * hp;
    g_h32[(size_t)(off_d + p) * HFEAT + j] = h;
    if (ls < NPC)                                         // parent of next level
        g_h16[(size_t)(off_d + p) * HFEAT + j] = __float2half_rn(h);
}

__global__ void leaf_max(float* __restrict__ out) {
    int t = blockIdx.x, j = threadIdx.x;
    float m = -3.402823466e+38f;
    const float* h5 = g_h32 + (size_t)(61952 + t * 243) * HFEAT;
    #pragma unroll 4
    for (int ls = 12; ls < 243; ++ls) m = fmaxf(m, h5[(size_t)ls * HFEAT + j]);
    const float* h6 = g_h32 + (size_t)(186368 + t * 36) * HFEAT;
    #pragma unroll 4
    for (int ls = 0; ls < 36; ++ls)   m = fmaxf(m, h6[(size_t)ls * HFEAT + j]);
    out[(size_t)t * HFEAT + j] = m;
}

// ---------------- launch -------------------------------------------------------
extern "C" void kernel_launch(void* const* d_in, const int* in_sizes, int n_in,
                              void* d_out, int out_size) {
    const float* inputs = (const float*)d_in[0];
    const float* W_ih   = (const float*)d_in[1];
    const float* W_hh   = (const float*)d_in[2];
    const float* b_ih   = (const float*)d_in[3];
    const float* b_hh   = (const float*)d_in[4];
    float* out = (float*)d_out;

    __half *p_gx16, *p_gh16, *p_x16, *p_wih, *p_whh, *p_h16;
    cudaGetSymbolAddress((void**)&p_gx16, g_gx16);
    cudaGetSymbolAddress((void**)&p_gh16, g_gh16);
    cudaGetSymbolAddress((void**)&p_x16,  g_x16);
    cudaGetSymbolAddress((void**)&p_wih,  g_wih);
    cudaGetSymbolAddress((void**)&p_whh,  g_whh);
    cudaGetSymbolAddress((void**)&p_h16,  g_h16);

    cudaFuncSetAttribute(gemm_h<INFEAT, false>,
                         cudaFuncAttributeMaxDynamicSharedMemorySize, SMEM_GX);
    cudaFuncSetAttribute(gemm_h<HFEAT, true>,
                         cudaFuncAttributeMaxDynamicSharedMemorySize, SMEM_GX);

    static const int cnt[7]   = {1, 3, 9, 27, 81, 243, 36};
    static const int start[7] = {0, 1, 4, 13, 40, 121, 364};
    static const int off[7]   = {0, 512, 2048, 6656, 20480, 61952, 186368};
    static const int PC[8]    = {0, 1, 3, 9, 27, 81, 12, 0};

    // 0) fp16 conversions
    f2h<<<(NNODES * INFEAT / 8 + 255) / 256, 256>>>(inputs, p_x16, NNODES * INFEAT / 8);
    f2h<<<(3 * HFEAT * INFEAT / 8 + 255) / 256, 256>>>(W_ih, p_wih, 3 * HFEAT * INFEAT / 8);
    f2h<<<(3 * HFEAT * HFEAT / 8 + 255) / 256, 256>>>(W_hh, p_whh, 3 * HFEAT * HFEAT / 8);

    // 1) gx = inputs @ W_ih^T + b_ih  (fp16 out)
    gemm_h<INFEAT, false><<<dim3(G3 / BN, NNODES / BM), NTHR, SMEM_GX>>>(
        p_x16, p_wih, b_ih, p_gx16, 1, 1);

    // 2) roots
    ew_level0<<<TREES, 256>>>(b_hh);

    // 3) levels 1..6: parent-subset gh GEMM (fp16 out, bias fused) + GRU ew
    for (int d = 1; d < 7; ++d) {
        int M = PC[d] * TREES;
        gemm_h<HFEAT, true><<<dim3(G3 / BN, M / BM), NTHR, SMEM_GX>>>(
            p_h16 + (size_t)off[d - 1] * HFEAT, p_whh, b_hh, p_gh16,
            PC[d], cnt[d - 1]);
        int R = cnt[d] * TREES;
        ew_level<<<R, 256>>>(cnt[d], cnt[d - 1], start[d], start[d - 1],
                             off[d], off[d - 1], PC[d], PC[d + 1]);
    }

    // 4) leaf max
    leaf_max<<<TREES, 256>>>(out);

    (void)in_sizes; (void)n_in; (void)out_size;
}